// round 14
// baseline (speedup 1.0000x reference)
#include <cuda_runtime.h>
#include <cuda_bf16.h>
#include <math.h>
#include <stdint.h>

// Problem constants
#define LSEQ 4096
#define DMODEL 1024
#define NHEAD 16
#define NAR 8
#define DHEAD 64
#define NCHUNK (DMODEL / 32)   // 32 K-chunks of 32 for GEMM

// 0.125 * log2(e): folded into Q so softmax can use exp2 (base-2 domain)
#define QSCALE_LOG2E 0.18033688011112042f

// ---------------------------------------------------------------------------
// Scratch (__device__ globals; no allocation allowed)
// ---------------------------------------------------------------------------
__device__ __nv_bfloat16 g_Ah[LSEQ * DMODEL];      // split of A operand (X, then O)
__device__ __nv_bfloat16 g_Al[LSEQ * DMODEL];
__device__ __nv_bfloat16 g_Bth[4 * DMODEL * DMODEL]; // transposed split weights [N,K] (Wq|Wk|Wv|Wo)
__device__ __nv_bfloat16 g_Btl[4 * DMODEL * DMODEL];
__device__ __nv_bfloat16 g_Qh[LSEQ * DMODEL];
__device__ __nv_bfloat16 g_Ql[LSEQ * DMODEL];
__device__ __nv_bfloat16 g_Kh[LSEQ * DMODEL];
__device__ __nv_bfloat16 g_Kl[LSEQ * DMODEL];
__device__ __nv_bfloat16 g_Vh[LSEQ * DMODEL];
__device__ __nv_bfloat16 g_Vl[LSEQ * DMODEL];
__device__ float2 g_rope[LSEQ * 32];               // cos/sin table

// ---------------------------------------------------------------------------
// PTX helpers (base sm_103-safe: mma.sync / ldmatrix / cp.async only)
// ---------------------------------------------------------------------------
__device__ __forceinline__ uint32_t smem_u32(const void* p) {
    uint32_t a;
    asm("{ .reg .u64 t; cvta.to.shared.u64 t, %1; cvt.u32.u64 %0, t; }"
        : "=r"(a) : "l"(p));
    return a;
}

#define CP16(dst, src) \
    asm volatile("cp.async.cg.shared.global [%0], [%1], 16;" \
                 :: "r"(dst), "l"(src) : "memory")
#define CP_COMMIT() asm volatile("cp.async.commit_group;" ::: "memory")

__device__ __forceinline__ void ldsm4(uint32_t* r, uint32_t addr) {
    asm volatile("ldmatrix.sync.aligned.m8n8.x4.shared.b16 {%0,%1,%2,%3}, [%4];"
                 : "=r"(r[0]), "=r"(r[1]), "=r"(r[2]), "=r"(r[3]) : "r"(addr));
}
__device__ __forceinline__ void ldsm4t(uint32_t* r, uint32_t addr) {
    asm volatile("ldmatrix.sync.aligned.m8n8.x4.trans.shared.b16 {%0,%1,%2,%3}, [%4];"
                 : "=r"(r[0]), "=r"(r[1]), "=r"(r[2]), "=r"(r[3]) : "r"(addr));
}

#define MMA16816(d, a, b)                                                       \
    asm volatile(                                                               \
        "mma.sync.aligned.m16n8k16.row.col.f32.bf16.bf16.f32 "                  \
        "{%0,%1,%2,%3}, {%4,%5,%6,%7}, {%8,%9}, {%0,%1,%2,%3};"                 \
        : "+f"((d)[0]), "+f"((d)[1]), "+f"((d)[2]), "+f"((d)[3])                \
        : "r"((a)[0]), "r"((a)[1]), "r"((a)[2]), "r"((a)[3]),                   \
          "r"((b)[0]), "r"((b)[1]))

// GEMM swizzle: rows of 32 bf16 (64B), 4 chunks of 16B
__device__ __forceinline__ uint32_t swz(int row, int chunk) {
    return (uint32_t)(row * 64 + ((chunk ^ ((row >> 1) & 3)) << 4));
}
// Flash swizzle: rows of 64 bf16 (128B), 8 chunks of 16B
__device__ __forceinline__ uint32_t swz8(int row, int chunk) {
    return (uint32_t)(row * 128 + ((chunk ^ (row & 7)) << 4));
}

__device__ __forceinline__ uint32_t pack_bf16x2(float lo, float hi) {
    uint32_t d;
    asm("cvt.rn.bf16x2.f32 %0, %1, %2;" : "=r"(d) : "f"(hi), "f"(lo));
    return d;
}

__device__ __forceinline__ float ex2(float x) {
    float y;
    asm("ex2.approx.ftz.f32 %0, %1;" : "=f"(y) : "f"(x));
    return y;
}

// Split one fp32 pair to hi/lo bf16x2 (fast path: 2 cvt + shift/mask + 2 sub)
__device__ __forceinline__ void split2(float x0, float x1,
                                       uint32_t& h, uint32_t& l) {
    h = pack_bf16x2(x0, x1);                      // {x1_hi : x0_lo}
    const float f0 = __uint_as_float(h << 16);
    const float f1 = __uint_as_float(h & 0xffff0000u);
    l = pack_bf16x2(x0 - f0, x1 - f1);
}

// ---------------------------------------------------------------------------
// Fused prep kernel: one launch does all independent preprocessing.
//   blocks [0, 4096):     transpose+split 4 weights (1024 blocks each)
//   blocks [4096, 8192):  X fp32 -> (Ah, Al) bf16 split
//   blocks [8192, 8704):  rope cos/sin table
// ---------------------------------------------------------------------------
__global__ void __launch_bounds__(256) prep_kernel(
    const float* __restrict__ X,
    const float* __restrict__ W0, const float* __restrict__ W1,
    const float* __restrict__ W2, const float* __restrict__ W3,
    __nv_bfloat16* __restrict__ bth, __nv_bfloat16* __restrict__ btl,
    __nv_bfloat16* __restrict__ ah, __nv_bfloat16* __restrict__ al,
    float2* __restrict__ tab) {
    __shared__ float s[32][33];
    const int bid = blockIdx.x;
    const int tid = threadIdx.x;

    if (bid < 4096) {
        // ---- weight transpose+split ----
        const int z = bid >> 10;
        const int r = bid & 1023;
        const float* W = (z == 0) ? W0 : (z == 1) ? W1 : (z == 2) ? W2 : W3;
        const int base = z * DMODEL * DMODEL;
        const int tx = tid & 31, ty = tid >> 5;
        const int n0 = (r & 31) * 32, k0 = (r >> 5) * 32;
#pragma unroll
        for (int j = 0; j < 4; j++)
            s[ty + j * 8][tx] = W[(k0 + ty + j * 8) * DMODEL + n0 + tx];
        __syncthreads();
#pragma unroll
        for (int j = 0; j < 4; j++) {
            float x = s[tx][ty + j * 8];
            __nv_bfloat16 h = __float2bfloat16(x);
            __nv_bfloat16 l = __float2bfloat16(x - __bfloat162float(h));
            int o = base + (n0 + ty + j * 8) * DMODEL + k0 + tx;
            bth[o] = h;
            btl[o] = l;
        }
    } else if (bid < 8192) {
        // ---- X split (float4 granularity) ----
        const int idx = (bid - 4096) * 256 + tid;
        float4 v = reinterpret_cast<const float4*>(X)[idx];
        uint32_t h0, l0, h1, l1;
        split2(v.x, v.y, h0, l0);
        split2(v.z, v.w, h1, l1);
        reinterpret_cast<uint32_t*>(ah)[idx * 2 + 0] = h0;
        reinterpret_cast<uint32_t*>(ah)[idx * 2 + 1] = h1;
        reinterpret_cast<uint32_t*>(al)[idx * 2 + 0] = l0;
        reinterpret_cast<uint32_t*>(al)[idx * 2 + 1] = l1;
    } else {
        // ---- rope table ----
        const int idx = (bid - 8192) * 256 + tid;  // 131072
        const int row = idx >> 5, jj = idx & 31;
        float invf = (float)pow(10000.0, -(double)jj / 32.0);
        float ang = (float)row * invf;  // fp32 product like jax
        double sn, cs;
        sincos((double)ang, &sn, &cs);
        tab[idx] = make_float2((float)cs, (float)sn);
    }
}

// ---------------------------------------------------------------------------
// Split kernel: fp32 -> (bf16 hi, bf16 lo)  (kept for generality; unused)
// ---------------------------------------------------------------------------

// ---------------------------------------------------------------------------
// GEMM mainloop, 128x256 CTA tile, 512 threads (16 warps, 4M x 4N),
// warp tile 32x64. 4-stage cp.async ring (R9 issue discipline, +1 depth).
// Stage layout: Ah 8K | Al 8K | Bh 16K | Bl 16K = 48KB. 4 stages = 192KB.
// ---------------------------------------------------------------------------
#define GEMM_SMEM 196608
#define STAGE_BYTES 49152u

#define GEMM_ISSUE(Ah_, Al_, Bh_, Bl_, chunk, buf)                               \
    do {                                                                         \
        const int _k0 = (chunk) * 32;                                            \
        const uint32_t _sbb = sb + (buf) * STAGE_BYTES;                          \
        const uint32_t _soa = swz(ra, ca);                                       \
        const size_t _ea = (size_t)(m0 + ra) * DMODEL + _k0 + ca * 8;            \
        CP16(_sbb + _soa,         (const void*)(Ah_ + _ea));                     \
        CP16(_sbb + 8192u + _soa, (const void*)(Al_ + _ea));                     \
        _Pragma("unroll")                                                        \
        for (int _r = 0; _r < 2; _r++) {                                         \
            const int _row = ra + _r * 128;                                      \
            const uint32_t _sob = swz(_row, ca);                                 \
            const size_t _eb = (size_t)(n0 + _row) * DMODEL + _k0 + ca * 8;      \
            CP16(_sbb + 16384u + _sob, (const void*)(Bh_ + _eb));                \
            CP16(_sbb + 32768u + _sob, (const void*)(Bl_ + _eb));                \
        }                                                                        \
        CP_COMMIT();                                                             \
    } while (0)

#define GEMM_MAINLOOP(Ah_, Al_, Bh_, Bl_)                                        \
    float acc[2][8][4];                                                          \
    _Pragma("unroll")                                                            \
    for (int a = 0; a < 2; a++)                                                  \
        _Pragma("unroll")                                                        \
        for (int n = 0; n < 8; n++)                                              \
            _Pragma("unroll")                                                    \
            for (int j = 0; j < 4; j++) acc[a][n][j] = 0.0f;                     \
    GEMM_ISSUE(Ah_, Al_, Bh_, Bl_, 0, 0);                                        \
    GEMM_ISSUE(Ah_, Al_, Bh_, Bl_, 1, 1);                                        \
    GEMM_ISSUE(Ah_, Al_, Bh_, Bl_, 2, 2);                                        \
    GEMM_ISSUE(Ah_, Al_, Bh_, Bl_, 3, 3);                                        \
    int stage = 0;                                                               \
    _Pragma("unroll 1")                                                          \
    for (int c = 0; c < NCHUNK; c++) {                                           \
        const int rem = NCHUNK - 1 - c;                                          \
        if (rem >= 3)                                                            \
            asm volatile("cp.async.wait_group 3;" ::: "memory");                 \
        else if (rem == 2)                                                       \
            asm volatile("cp.async.wait_group 2;" ::: "memory");                 \
        else if (rem == 1)                                                       \
            asm volatile("cp.async.wait_group 1;" ::: "memory");                 \
        else                                                                     \
            asm volatile("cp.async.wait_group 0;" ::: "memory");                 \
        __syncthreads();                                                         \
        const uint32_t ab = sb + stage * STAGE_BYTES;                            \
        const uint32_t bbb = ab + 16384u;                                        \
        _Pragma("unroll")                                                        \
        for (int ks = 0; ks < 2; ks++) {                                         \
            uint32_t ah_[2][4], al_[2][4];                                       \
            _Pragma("unroll")                                                    \
            for (int a = 0; a < 2; a++) {                                        \
                const int row = wm + a * 16 + ((lane >> 3) & 1) * 8 + (lane & 7);\
                const int ch = ks * 2 + (lane >> 4);                             \
                const uint32_t off = swz(row, ch);                               \
                ldsm4(ah_[a], ab + off);                                         \
                ldsm4(al_[a], ab + 8192u + off);                                 \
            }                                                                    \
            _Pragma("unroll")                                                    \
            for (int g = 0; g < 4; g++) {                                        \
                const int row = wn + g * 16 + ((lane >> 4) & 1) * 8 + (lane & 7);\
                const int ch = ks * 2 + ((lane >> 3) & 1);                       \
                const uint32_t off = swz(row, ch);                               \
                uint32_t bh[4], bl[4];                                           \
                ldsm4(bh, bbb + off);                                            \
                _Pragma("unroll")                                                \
                for (int a = 0; a < 2; a++) {                                    \
                    MMA16816(acc[a][2 * g + 0], ah_[a], bh + 0);                 \
                    MMA16816(acc[a][2 * g + 1], ah_[a], bh + 2);                 \
                    MMA16816(acc[a][2 * g + 0], al_[a], bh + 0);                 \
                    MMA16816(acc[a][2 * g + 1], al_[a], bh + 2);                 \
                }                                                                \
                ldsm4(bl, bbb + 16384u + off);                                   \
                _Pragma("unroll")                                                \
                for (int a = 0; a < 2; a++) {                                    \
                    MMA16816(acc[a][2 * g + 0], ah_[a], bl + 0);                 \
                    MMA16816(acc[a][2 * g + 1], ah_[a], bl + 2);                 \
                }                                                                \
            }                                                                    \
        }                                                                        \
        __syncthreads();                                                         \
        if (c + 4 < NCHUNK) {                                                    \
            GEMM_ISSUE(Ah_, Al_, Bh_, Bl_, c + 4, stage);                        \
        }                                                                        \
        stage = (stage + 1) & 3;                                                 \
    }

// ---------------------------------------------------------------------------
// Plain GEMM: fp32 C output (final projection). Grid (4, 32). 512 threads.
// ---------------------------------------------------------------------------
__global__ void __launch_bounds__(512, 1) gemm_mma(
    const __nv_bfloat16* __restrict__ Ah, const __nv_bfloat16* __restrict__ Al,
    const __nv_bfloat16* __restrict__ Bh, const __nv_bfloat16* __restrict__ Bl,
    float* __restrict__ C) {
    extern __shared__ char sm[];
    const uint32_t sb = smem_u32(sm);
    const int tid = threadIdx.x;
    const int wid = tid >> 5, lane = tid & 31;
    const int wm = (wid & 3) * 32;
    const int wn = (wid >> 2) * 64;
    const int ra = tid >> 2;          // loader row 0..127
    const int ca = tid & 3;           // loader 16B chunk 0..3
    const int m0 = blockIdx.y << 7;
    const int n0 = blockIdx.x << 8;

    GEMM_MAINLOOP(Ah, Al, Bh, Bl)

    const int er = lane >> 2;
    const int ec = (lane & 3) * 2;
#pragma unroll
    for (int a = 0; a < 2; a++) {
#pragma unroll
        for (int n = 0; n < 8; n++) {
            float* p0 = C + (size_t)(m0 + wm + a * 16 + er) * DMODEL + n0 + wn + n * 8 + ec;
            float* p1 = p0 + 8 * DMODEL;
            *reinterpret_cast<float2*>(p0) = make_float2(acc[a][n][0], acc[a][n][1]);
            *reinterpret_cast<float2*>(p1) = make_float2(acc[a][n][2], acc[a][n][3]);
        }
    }
}

// ---------------------------------------------------------------------------
// Fused QKV GEMM: grid (12, 32), N=3072 (Q|K|V; 256-wide CTAs never straddle).
// Epilogue applies RoPE to Q,K, folds 0.125*log2(e) into Q, writes split bf16.
// ---------------------------------------------------------------------------
__global__ void __launch_bounds__(512, 1) gemm_qkv(
    const __nv_bfloat16* __restrict__ Ah, const __nv_bfloat16* __restrict__ Al,
    const __nv_bfloat16* __restrict__ Bh, const __nv_bfloat16* __restrict__ Bl,
    const float2* __restrict__ tab,
    __nv_bfloat16* __restrict__ Qh, __nv_bfloat16* __restrict__ Ql,
    __nv_bfloat16* __restrict__ Kh, __nv_bfloat16* __restrict__ Kl,
    __nv_bfloat16* __restrict__ Vh, __nv_bfloat16* __restrict__ Vl) {
    extern __shared__ char sm[];
    const uint32_t sb = smem_u32(sm);
    const int tid = threadIdx.x;
    const int wid = tid >> 5, lane = tid & 31;
    const int wm = (wid & 3) * 32;
    const int wn = (wid >> 2) * 64;
    const int ra = tid >> 2;
    const int ca = tid & 3;
    const int m0 = blockIdx.y << 7;
    const int n0 = blockIdx.x << 8;

    GEMM_MAINLOOP(Ah, Al, Bh, Bl)

    const int er = lane >> 2;
    const int ec = (lane & 3) * 2;
    const int qkv = n0 >> 10;          // 0=Q, 1=K, 2=V (n0 multiple of 256)
    const int ncol = (n0 & 1023) + wn; // col offset within this output

    if (qkv < 2) {
        __nv_bfloat16* Dh = (qkv == 0) ? Qh : Kh;
        __nv_bfloat16* Dl = (qkv == 0) ? Ql : Kl;
        const float post = (qkv == 0) ? QSCALE_LOG2E : 1.0f;
#pragma unroll
        for (int a = 0; a < 2; a++) {
#pragma unroll
            for (int nf = 0; nf < 4; nf++) {   // pair (nf, nf+4) = cols jj, jj+32
                const int jj0 = nf * 8 + ec;
                const int dcol = ncol + nf * 8 + ec;
#pragma unroll
                for (int rs = 0; rs < 2; rs++) {
                    const int row = m0 + wm + a * 16 + er + rs * 8;
                    const float x1_0 = acc[a][nf][rs * 2 + 0];
                    const float x1_1 = acc[a][nf][rs * 2 + 1];
                    const float x2_0 = acc[a][nf + 4][rs * 2 + 0];
                    const float x2_1 = acc[a][nf + 4][rs * 2 + 1];
                    const float2 cs0 = tab[row * 32 + jj0];
                    const float2 cs1 = tab[row * 32 + jj0 + 1];
                    const float y1_0 = fmaf(x1_0, cs0.x, -x2_0 * cs0.y) * post;
                    const float y2_0 = fmaf(x2_0, cs0.x,  x1_0 * cs0.y) * post;
                    const float y1_1 = fmaf(x1_1, cs1.x, -x2_1 * cs1.y) * post;
                    const float y2_1 = fmaf(x2_1, cs1.x,  x1_1 * cs1.y) * post;
                    uint32_t h1, l1, h2, l2;
                    split2(y1_0, y1_1, h1, l1);
                    split2(y2_0, y2_1, h2, l2);
                    const size_t o1 = (size_t)row * DMODEL + dcol;
                    *reinterpret_cast<uint32_t*>(Dh + o1) = h1;
                    *reinterpret_cast<uint32_t*>(Dl + o1) = l1;
                    *reinterpret_cast<uint32_t*>(Dh + o1 + 32) = h2;
                    *reinterpret_cast<uint32_t*>(Dl + o1 + 32) = l2;
                }
            }
        }
    } else {
#pragma unroll
        for (int a = 0; a < 2; a++) {
#pragma unroll
            for (int nf = 0; nf < 8; nf++) {
                const int dcol = ncol + nf * 8 + ec;
#pragma unroll
                for (int rs = 0; rs < 2; rs++) {
                    const int row = m0 + wm + a * 16 + er + rs * 8;
                    uint32_t h, l;
                    split2(acc[a][nf][rs * 2 + 0], acc[a][nf][rs * 2 + 1], h, l);
                    const size_t o1 = (size_t)row * DMODEL + dcol;
                    *reinterpret_cast<uint32_t*>(Vh + o1) = h;
                    *reinterpret_cast<uint32_t*>(Vl + o1) = l;
                }
            }
        }
    }
}

// ---------------------------------------------------------------------------
// HMMA flash attention, 256 threads (8 warps x 16 q-rows), 128-q tile.
// 2 CTAs/SM. Q pre-scaled by 0.125*log2(e) -> base-2 softmax via ex2.approx.
// ---------------------------------------------------------------------------
#define FLASH_SMEM 98304

__global__ void __launch_bounds__(256, 2) flash_mma(
    const __nv_bfloat16* __restrict__ Qh, const __nv_bfloat16* __restrict__ Ql,
    const __nv_bfloat16* __restrict__ Kh, const __nv_bfloat16* __restrict__ Kl,
    const __nv_bfloat16* __restrict__ Vh, const __nv_bfloat16* __restrict__ Vl,
    __nv_bfloat16* __restrict__ Oh, __nv_bfloat16* __restrict__ Ol) {
    extern __shared__ char sm[];
    const uint32_t sb = smem_u32(sm);
    const int tid = threadIdx.x;
    const int wid = tid >> 5, lane = tid & 31;

    // Work-ordered schedule: heavy CTAs dispatch first.
    const int bid = blockIdx.x;
    int h, qt;
    if (bid < 256) {           // full-attention heads: 64 kv tiles each
        h = 8 + (bid & 7);
        qt = bid >> 3;
    } else {                   // causal heads: descending qt (descending work)
        const int cid = bid - 256;
        qt = 31 - (cid >> 3);
        h = cid & 7;
    }
    const bool causal = (h < NAR);
    const int wm = wid * 16;

    // ---- load Q tile (128 rows, head slice), both splits ----
    {
        const int row = tid >> 1;
        const int chb = (tid & 1) * 4;
        const size_t g = (size_t)(qt * 128 + row) * DMODEL + h * DHEAD;
#pragma unroll
        for (int j = 0; j < 4; j++) {
            const uint32_t so = swz8(row, chb + j);
            CP16(sb + so, (const void*)(Qh + g + (chb + j) * 8));
            CP16(sb + 16384u + so, (const void*)(Ql + g + (chb + j) * 8));
        }
    }
    CP_COMMIT();

    const int ktiles = causal ? (2 * qt + 2) : (LSEQ / 64);

#define ISSUEKV(kt, buf)                                                        \
    do {                                                                        \
        const int _row = tid >> 2;                                              \
        const int _cb = (tid & 3) * 2;                                          \
        const uint32_t _sbb = sb + 32768u + (buf) * 32768u;                     \
        const size_t _g = (size_t)((kt) * 64 + _row) * DMODEL + h * DHEAD;      \
        _Pragma("unroll")                                                       \
        for (int _j = 0; _j < 2; _j++) {                                        \
            const uint32_t _so = swz8(_row, _cb + _j);                          \
            const size_t _e = _g + (_cb + _j) * 8;                              \
            CP16(_sbb + _so,           (const void*)(Kh + _e));                 \
            CP16(_sbb + 8192u + _so,   (const void*)(Kl + _e));                 \
            CP16(_sbb + 16384u + _so,  (const void*)(Vh + _e));                 \
            CP16(_sbb + 24576u + _so,  (const void*)(Vl + _e));                 \
        }                                                                       \
    } while (0)

    ISSUEKV(0, 0);
    CP_COMMIT();
    ISSUEKV(1, 1);
    CP_COMMIT();

    float o[8][4];
#pragma unroll
    for (int n = 0; n < 8; n++)
#pragma unroll
        for (int j = 0; j < 4; j++) o[n][j] = 0.0f;
    float m_[2] = {-1e30f, -1e30f};
    float l_[2] = {0.0f, 0.0f};

#pragma unroll 1
    for (int kt = 0; kt < ktiles; kt++) {
        if (kt < ktiles - 1)
            asm volatile("cp.async.wait_group 1;" ::: "memory");
        else
            asm volatile("cp.async.wait_group 0;" ::: "memory");
        __syncthreads();

        const uint32_t kbase = sb + 32768u + (kt & 1) * 32768u;
        const uint32_t vbase = kbase + 16384u;

        // ---- S = Q K^T (3 split terms); Q pre-scaled (base-2 domain) ----
        float sv[8][4];
#pragma unroll
        for (int n = 0; n < 8; n++)
#pragma unroll
            for (int j = 0; j < 4; j++) sv[n][j] = 0.0f;

#pragma unroll
        for (int ks = 0; ks < 4; ks++) {
            uint32_t ah[4], al[4];
            {
                const int row = wm + ((lane >> 3) & 1) * 8 + (lane & 7);
                const int ch = ks * 2 + (lane >> 4);
                const uint32_t off = swz8(row, ch);
                ldsm4(ah, sb + off);
                ldsm4(al, sb + 16384u + off);
            }
#pragma unroll
            for (int g = 0; g < 4; g++) {
                const int krow = g * 16 + ((lane >> 4) & 1) * 8 + (lane & 7);
                const int kch = ks * 2 + ((lane >> 3) & 1);
                const uint32_t off = swz8(krow, kch);
                uint32_t kh[4], kl[4];
                ldsm4(kh, kbase + off);
                MMA16816(sv[2 * g + 0], ah, kh + 0);
                MMA16816(sv[2 * g + 1], ah, kh + 2);
                MMA16816(sv[2 * g + 0], al, kh + 0);
                MMA16816(sv[2 * g + 1], al, kh + 2);
                ldsm4(kl, kbase + 8192u + off);
                MMA16816(sv[2 * g + 0], ah, kl + 0);
                MMA16816(sv[2 * g + 1], ah, kl + 2);
            }
        }

        // ---- causal mask ----
        if (causal && kt >= 2 * qt) {
#pragma unroll
            for (int half = 0; half < 2; half++) {
                const int qg = qt * 128 + wm + (lane >> 2) + half * 8;
#pragma unroll
                for (int nf = 0; nf < 8; nf++) {
#pragma unroll
                    for (int j = 0; j < 2; j++) {
                        const int kv = kt * 64 + nf * 8 + (lane & 3) * 2 + j;
                        if (kv > qg) sv[nf][half * 2 + j] = -1e30f;
                    }
                }
            }
        }

        // ---- online softmax, base-2 (2 rows per thread) ----
        float mnew[2];
#pragma unroll
        for (int half = 0; half < 2; half++) {
            float mx = -1e30f;
#pragma unroll
            for (int nf = 0; nf < 8; nf++)
                mx = fmaxf(mx, fmaxf(sv[nf][half * 2], sv[nf][half * 2 + 1]));
            mnew[half] = mx;
        }
#pragma unroll
        for (int r = 0; r < 2; r++) {
            mnew[r] = fmaxf(mnew[r], __shfl_xor_sync(0xffffffffu, mnew[r], 1));
            mnew[r] = fmaxf(mnew[r], __shfl_xor_sync(0xffffffffu, mnew[r], 2));
        }

        float alpha[2];
#pragma unroll
        for (int r = 0; r < 2; r++) {
            float mt = fmaxf(m_[r], mnew[r]);
            alpha[r] = ex2(m_[r] - mt);
            m_[r] = mt;
        }

        float rsum[2] = {0.0f, 0.0f};
#pragma unroll
        for (int nf = 0; nf < 8; nf++) {
#pragma unroll
            for (int half = 0; half < 2; half++) {
#pragma unroll
                for (int j = 0; j < 2; j++) {
                    float p = ex2(sv[nf][half * 2 + j] - m_[half]);
                    sv[nf][half * 2 + j] = p;
                    rsum[half] += p;
                }
            }
        }
#pragma unroll
        for (int r = 0; r < 2; r++) {
            rsum[r] += __shfl_xor_sync(0xffffffffu, rsum[r], 1);
            rsum[r] += __shfl_xor_sync(0xffffffffu, rsum[r], 2);
            l_[r] = l_[r] * alpha[r] + rsum[r];
        }

        // Rescale o only when the running max actually moved (warp vote).
        const bool need_rescale = (alpha[0] != 1.0f) || (alpha[1] != 1.0f);
        if (__any_sync(0xffffffffu, need_rescale)) {
#pragma unroll
            for (int nf = 0; nf < 8; nf++)
#pragma unroll
                for (int half = 0; half < 2; half++) {
                    o[nf][half * 2 + 0] *= alpha[half];
                    o[nf][half * 2 + 1] *= alpha[half];
                }
        }

        // ---- O += P V (3 split terms) ----
#pragma unroll
        for (int kg = 0; kg < 4; kg++) {
            uint32_t ph[4], pl[4];
#pragma unroll
            for (int q = 0; q < 2; q++) {
                const int nf = 2 * kg + q;
#pragma unroll
                for (int half = 0; half < 2; half++) {
                    float p0 = sv[nf][half * 2 + 0];
                    float p1 = sv[nf][half * 2 + 1];
                    split2(p0, p1, ph[q * 2 + half], pl[q * 2 + half]);
                }
            }
#pragma unroll
            for (int gd = 0; gd < 4; gd++) {
                const int vrow = kg * 16 + (lane & 15);
                const int vch = gd * 2 + (lane >> 4);
                const uint32_t off = swz8(vrow, vch);
                uint32_t vh[4], vl[4];
                ldsm4t(vh, vbase + off);
                MMA16816(o[2 * gd + 0], ph, vh + 0);
                MMA16816(o[2 * gd + 1], ph, vh + 2);
                MMA16816(o[2 * gd + 0], pl, vh + 0);
                MMA16816(o[2 * gd + 1], pl, vh + 2);
                ldsm4t(vl, vbase + 8192u + off);
                MMA16816(o[2 * gd + 0], ph, vl + 0);
                MMA16816(o[2 * gd + 1], ph, vl + 2);
            }
        }

        __syncthreads();
        if (kt + 2 < ktiles) {
            ISSUEKV(kt + 2, kt & 1);
            CP_COMMIT();
        }
    }
#undef ISSUEKV

    // ---- epilogue: normalize and store split bf16 O (into Ah/Al) ----
    const float inva = 1.0f / l_[0];
    const float invb = 1.0f / l_[1];
    const int rowa = qt * 128 + wm + (lane >> 2);
#pragma unroll
    for (int nf = 0; nf < 8; nf++) {
        const int col = h * DHEAD + nf * 8 + (lane & 3) * 2;
        uint32_t hA, lA, hB, lB;
        split2(o[nf][0] * inva, o[nf][1] * inva, hA, lA);
        split2(o[nf][2] * invb, o[nf][3] * invb, hB, lB);
        const size_t oa = (size_t)rowa * DMODEL + col;
        const size_t ob = oa + 8 * DMODEL;
        *reinterpret_cast<uint32_t*>(Oh + oa) = hA;
        *reinterpret_cast<uint32_t*>(Ol + oa) = lA;
        *reinterpret_cast<uint32_t*>(Oh + ob) = hB;
        *reinterpret_cast<uint32_t*>(Ol + ob) = lB;
    }
}

// ---------------------------------------------------------------------------
// Launch
// ---------------------------------------------------------------------------
extern "C" void kernel_launch(void* const* d_in, const int* in_sizes, int n_in,
                              void* d_out, int out_size) {
    const float* X  = (const float*)d_in[0];
    const float* Wq = (const float*)d_in[1];
    const float* Wk = (const float*)d_in[2];
    const float* Wv = (const float*)d_in[3];
    const float* Wo = (const float*)d_in[4];
    float* out = (float*)d_out;

    float2* ropep;
    __nv_bfloat16 *Ahp, *Alp, *Bthp, *Btlp;
    __nv_bfloat16 *Qhp, *Qlp, *Khp, *Klp, *Vhp, *Vlp;
    cudaGetSymbolAddress((void**)&ropep, g_rope);
    cudaGetSymbolAddress((void**)&Ahp, g_Ah);
    cudaGetSymbolAddress((void**)&Alp, g_Al);
    cudaGetSymbolAddress((void**)&Bthp, g_Bth);
    cudaGetSymbolAddress((void**)&Btlp, g_Btl);
    cudaGetSymbolAddress((void**)&Qhp, g_Qh);
    cudaGetSymbolAddress((void**)&Qlp, g_Ql);
    cudaGetSymbolAddress((void**)&Khp, g_Kh);
    cudaGetSymbolAddress((void**)&Klp, g_Kl);
    cudaGetSymbolAddress((void**)&Vhp, g_Vh);
    cudaGetSymbolAddress((void**)&Vlp, g_Vl);

    cudaFuncSetAttribute(gemm_mma, cudaFuncAttributeMaxDynamicSharedMemorySize,
                         GEMM_SMEM);
    cudaFuncSetAttribute(gemm_qkv, cudaFuncAttributeMaxDynamicSharedMemorySize,
                         GEMM_SMEM);
    cudaFuncSetAttribute(flash_mma, cudaFuncAttributeMaxDynamicSharedMemorySize,
                         FLASH_SMEM);

    // One fused prep launch: weight transposes+splits, X split, rope table
    prep_kernel<<<8704, 256>>>(X, Wq, Wk, Wv, Wo, Bthp, Btlp, Ahp, Alp, ropep);

    // Fused QKV GEMM with rope+scale+split epilogue (128x256 tiles)
    dim3 qkv_grid(3 * DMODEL / 256, LSEQ / 128);  // (12, 32)
    gemm_qkv<<<qkv_grid, 512, GEMM_SMEM>>>(Ahp, Alp, Bthp, Btlp, ropep,
                                           Qhp, Qlp, Khp, Klp, Vhp, Vlp);

    // Flash attention; writes split O into Ah/Al. Work-ordered 1D grid.
    flash_mma<<<512, 256, FLASH_SMEM>>>(Qhp, Qlp, Khp, Klp, Vhp, Vlp,
                                        Ahp, Alp);

    // Final projection (Wo at slot 3), 128x256 tiles
    dim3 gemm_grid(DMODEL / 256, LSEQ / 128);  // (4, 32)
    gemm_mma<<<gemm_grid, 512, GEMM_SMEM>>>(Ahp, Alp,
                                            Bthp + 3 * DMODEL * DMODEL,
                                            Btlp + 3 * DMODEL * DMODEL, out);
}

// round 15
// speedup vs baseline: 1.0260x; 1.0260x over previous
#include <cuda_runtime.h>
#include <cuda_bf16.h>
#include <math.h>
#include <stdint.h>

// Problem constants
#define LSEQ 4096
#define DMODEL 1024
#define NHEAD 16
#define NAR 8
#define DHEAD 64
#define NCHUNK (DMODEL / 32)   // 32 K-chunks of 32 for GEMM

// 0.125 * log2(e): folded into Q so softmax can use exp2 (base-2 domain)
#define QSCALE_LOG2E 0.18033688011112042f

// ---------------------------------------------------------------------------
// Scratch (__device__ globals; no allocation allowed)
// ---------------------------------------------------------------------------
__device__ __nv_bfloat16 g_Ah[LSEQ * DMODEL];      // split of A operand (X, then O)
__device__ __nv_bfloat16 g_Al[LSEQ * DMODEL];
__device__ __nv_bfloat16 g_Bth[4 * DMODEL * DMODEL]; // transposed split weights [N,K] (Wq|Wk|Wv|Wo)
__device__ __nv_bfloat16 g_Btl[4 * DMODEL * DMODEL];
__device__ __nv_bfloat16 g_Qh[LSEQ * DMODEL];
__device__ __nv_bfloat16 g_Ql[LSEQ * DMODEL];
__device__ __nv_bfloat16 g_Kh[LSEQ * DMODEL];
__device__ __nv_bfloat16 g_Kl[LSEQ * DMODEL];
__device__ __nv_bfloat16 g_Vh[LSEQ * DMODEL];
__device__ __nv_bfloat16 g_Vl[LSEQ * DMODEL];
__device__ float2 g_rope[LSEQ * 32];               // cos/sin table

// ---------------------------------------------------------------------------
// PTX helpers (base sm_103-safe: mma.sync / ldmatrix / cp.async only)
// ---------------------------------------------------------------------------
__device__ __forceinline__ uint32_t smem_u32(const void* p) {
    uint32_t a;
    asm("{ .reg .u64 t; cvta.to.shared.u64 t, %1; cvt.u32.u64 %0, t; }"
        : "=r"(a) : "l"(p));
    return a;
}

#define CP16(dst, src) \
    asm volatile("cp.async.cg.shared.global [%0], [%1], 16;" \
                 :: "r"(dst), "l"(src) : "memory")
#define CP_COMMIT() asm volatile("cp.async.commit_group;" ::: "memory")

__device__ __forceinline__ void ldsm4(uint32_t* r, uint32_t addr) {
    asm volatile("ldmatrix.sync.aligned.m8n8.x4.shared.b16 {%0,%1,%2,%3}, [%4];"
                 : "=r"(r[0]), "=r"(r[1]), "=r"(r[2]), "=r"(r[3]) : "r"(addr));
}
__device__ __forceinline__ void ldsm4t(uint32_t* r, uint32_t addr) {
    asm volatile("ldmatrix.sync.aligned.m8n8.x4.trans.shared.b16 {%0,%1,%2,%3}, [%4];"
                 : "=r"(r[0]), "=r"(r[1]), "=r"(r[2]), "=r"(r[3]) : "r"(addr));
}

#define MMA16816(d, a, b)                                                       \
    asm volatile(                                                               \
        "mma.sync.aligned.m16n8k16.row.col.f32.bf16.bf16.f32 "                  \
        "{%0,%1,%2,%3}, {%4,%5,%6,%7}, {%8,%9}, {%0,%1,%2,%3};"                 \
        : "+f"((d)[0]), "+f"((d)[1]), "+f"((d)[2]), "+f"((d)[3])                \
        : "r"((a)[0]), "r"((a)[1]), "r"((a)[2]), "r"((a)[3]),                   \
          "r"((b)[0]), "r"((b)[1]))

// GEMM swizzle: rows of 32 bf16 (64B), 4 chunks of 16B
__device__ __forceinline__ uint32_t swz(int row, int chunk) {
    return (uint32_t)(row * 64 + ((chunk ^ ((row >> 1) & 3)) << 4));
}
// Flash swizzle: rows of 64 bf16 (128B), 8 chunks of 16B
__device__ __forceinline__ uint32_t swz8(int row, int chunk) {
    return (uint32_t)(row * 128 + ((chunk ^ (row & 7)) << 4));
}

__device__ __forceinline__ uint32_t pack_bf16x2(float lo, float hi) {
    uint32_t d;
    asm("cvt.rn.bf16x2.f32 %0, %1, %2;" : "=r"(d) : "f"(hi), "f"(lo));
    return d;
}

__device__ __forceinline__ float ex2(float x) {
    float y;
    asm("ex2.approx.ftz.f32 %0, %1;" : "=f"(y) : "f"(x));
    return y;
}

// Split one fp32 pair to hi/lo bf16x2 (fast path: 2 cvt + shift/mask + 2 sub)
__device__ __forceinline__ void split2(float x0, float x1,
                                       uint32_t& h, uint32_t& l) {
    h = pack_bf16x2(x0, x1);                      // {x1_hi : x0_lo}
    const float f0 = __uint_as_float(h << 16);
    const float f1 = __uint_as_float(h & 0xffff0000u);
    l = pack_bf16x2(x0 - f0, x1 - f1);
}

// ---------------------------------------------------------------------------
// Split kernel: fp32 -> (bf16 hi, bf16 lo)  (used for X only)
// ---------------------------------------------------------------------------
__global__ void __launch_bounds__(256) split_kernel(const float* __restrict__ src,
                                                    __nv_bfloat16* __restrict__ hi,
                                                    __nv_bfloat16* __restrict__ lo) {
    int idx = blockIdx.x * 256 + threadIdx.x;  // over float4s
    float4 v = reinterpret_cast<const float4*>(src)[idx];
    uint32_t h0, l0, h1, l1;
    split2(v.x, v.y, h0, l0);
    split2(v.z, v.w, h1, l1);
    reinterpret_cast<uint32_t*>(hi)[idx * 2 + 0] = h0;
    reinterpret_cast<uint32_t*>(hi)[idx * 2 + 1] = h1;
    reinterpret_cast<uint32_t*>(lo)[idx * 2 + 0] = l0;
    reinterpret_cast<uint32_t*>(lo)[idx * 2 + 1] = l1;
}

// ---------------------------------------------------------------------------
// Transpose+split all 4 weights in ONE launch (z selects weight).
// ---------------------------------------------------------------------------
__global__ void __launch_bounds__(256) wsplit_all_kernel(
    const float* __restrict__ W0, const float* __restrict__ W1,
    const float* __restrict__ W2, const float* __restrict__ W3,
    __nv_bfloat16* __restrict__ bth, __nv_bfloat16* __restrict__ btl) {
    __shared__ float s[32][33];
    const int z = blockIdx.z;
    const float* W = (z == 0) ? W0 : (z == 1) ? W1 : (z == 2) ? W2 : W3;
    const int base = z * DMODEL * DMODEL;
    int tx = threadIdx.x & 31, ty = threadIdx.x >> 5;
    int n0 = blockIdx.x * 32, k0 = blockIdx.y * 32;
#pragma unroll
    for (int j = 0; j < 4; j++)
        s[ty + j * 8][tx] = W[(k0 + ty + j * 8) * DMODEL + n0 + tx];
    __syncthreads();
#pragma unroll
    for (int j = 0; j < 4; j++) {
        float x = s[tx][ty + j * 8];
        __nv_bfloat16 h = __float2bfloat16(x);
        __nv_bfloat16 l = __float2bfloat16(x - __bfloat162float(h));
        int o = base + (n0 + ty + j * 8) * DMODEL + k0 + tx;
        bth[o] = h;
        btl[o] = l;
    }
}

// ---------------------------------------------------------------------------
// GEMM mainloop, 128x256 CTA tile, 512 threads (16 warps, 4M x 4N),
// warp tile 32x64. 4-stage cp.async ring (R9 issue discipline, +1 depth).
// Stage layout: Ah 8K | Al 8K | Bh 16K | Bl 16K = 48KB. 4 stages = 192KB.
// ---------------------------------------------------------------------------
#define GEMM_SMEM 196608
#define STAGE_BYTES 49152u

#define GEMM_ISSUE(Ah_, Al_, Bh_, Bl_, chunk, buf)                               \
    do {                                                                         \
        const int _k0 = (chunk) * 32;                                            \
        const uint32_t _sbb = sb + (buf) * STAGE_BYTES;                          \
        const uint32_t _soa = swz(ra, ca);                                       \
        const size_t _ea = (size_t)(m0 + ra) * DMODEL + _k0 + ca * 8;            \
        CP16(_sbb + _soa,         (const void*)(Ah_ + _ea));                     \
        CP16(_sbb + 8192u + _soa, (const void*)(Al_ + _ea));                     \
        _Pragma("unroll")                                                        \
        for (int _r = 0; _r < 2; _r++) {                                         \
            const int _row = ra + _r * 128;                                      \
            const uint32_t _sob = swz(_row, ca);                                 \
            const size_t _eb = (size_t)(n0 + _row) * DMODEL + _k0 + ca * 8;      \
            CP16(_sbb + 16384u + _sob, (const void*)(Bh_ + _eb));                \
            CP16(_sbb + 32768u + _sob, (const void*)(Bl_ + _eb));                \
        }                                                                        \
        CP_COMMIT();                                                             \
    } while (0)

#define GEMM_MAINLOOP(Ah_, Al_, Bh_, Bl_)                                        \
    float acc[2][8][4];                                                          \
    _Pragma("unroll")                                                            \
    for (int a = 0; a < 2; a++)                                                  \
        _Pragma("unroll")                                                        \
        for (int n = 0; n < 8; n++)                                              \
            _Pragma("unroll")                                                    \
            for (int j = 0; j < 4; j++) acc[a][n][j] = 0.0f;                     \
    GEMM_ISSUE(Ah_, Al_, Bh_, Bl_, 0, 0);                                        \
    GEMM_ISSUE(Ah_, Al_, Bh_, Bl_, 1, 1);                                        \
    GEMM_ISSUE(Ah_, Al_, Bh_, Bl_, 2, 2);                                        \
    GEMM_ISSUE(Ah_, Al_, Bh_, Bl_, 3, 3);                                        \
    int stage = 0;                                                               \
    _Pragma("unroll 1")                                                          \
    for (int c = 0; c < NCHUNK; c++) {                                           \
        const int rem = NCHUNK - 1 - c;                                          \
        if (rem >= 3)                                                            \
            asm volatile("cp.async.wait_group 3;" ::: "memory");                 \
        else if (rem == 2)                                                       \
            asm volatile("cp.async.wait_group 2;" ::: "memory");                 \
        else if (rem == 1)                                                       \
            asm volatile("cp.async.wait_group 1;" ::: "memory");                 \
        else                                                                     \
            asm volatile("cp.async.wait_group 0;" ::: "memory");                 \
        __syncthreads();                                                         \
        const uint32_t ab = sb + stage * STAGE_BYTES;                            \
        const uint32_t bbb = ab + 16384u;                                        \
        _Pragma("unroll")                                                        \
        for (int ks = 0; ks < 2; ks++) {                                         \
            uint32_t ah_[2][4], al_[2][4];                                       \
            _Pragma("unroll")                                                    \
            for (int a = 0; a < 2; a++) {                                        \
                const int row = wm + a * 16 + ((lane >> 3) & 1) * 8 + (lane & 7);\
                const int ch = ks * 2 + (lane >> 4);                             \
                const uint32_t off = swz(row, ch);                               \
                ldsm4(ah_[a], ab + off);                                         \
                ldsm4(al_[a], ab + 8192u + off);                                 \
            }                                                                    \
            _Pragma("unroll")                                                    \
            for (int g = 0; g < 4; g++) {                                        \
                const int row = wn + g * 16 + ((lane >> 4) & 1) * 8 + (lane & 7);\
                const int ch = ks * 2 + ((lane >> 3) & 1);                       \
                const uint32_t off = swz(row, ch);                               \
                uint32_t bh[4], bl[4];                                           \
                ldsm4(bh, bbb + off);                                            \
                _Pragma("unroll")                                                \
                for (int a = 0; a < 2; a++) {                                    \
                    MMA16816(acc[a][2 * g + 0], ah_[a], bh + 0);                 \
                    MMA16816(acc[a][2 * g + 1], ah_[a], bh + 2);                 \
                    MMA16816(acc[a][2 * g + 0], al_[a], bh + 0);                 \
                    MMA16816(acc[a][2 * g + 1], al_[a], bh + 2);                 \
                }                                                                \
                ldsm4(bl, bbb + 16384u + off);                                   \
                _Pragma("unroll")                                                \
                for (int a = 0; a < 2; a++) {                                    \
                    MMA16816(acc[a][2 * g + 0], ah_[a], bl + 0);                 \
                    MMA16816(acc[a][2 * g + 1], ah_[a], bl + 2);                 \
                }                                                                \
            }                                                                    \
        }                                                                        \
        __syncthreads();                                                         \
        if (c + 4 < NCHUNK) {                                                    \
            GEMM_ISSUE(Ah_, Al_, Bh_, Bl_, c + 4, stage);                        \
        }                                                                        \
        stage = (stage + 1) & 3;                                                 \
    }

// ---------------------------------------------------------------------------
// Plain GEMM: fp32 C output (final projection). Grid (4, 32). 512 threads.
// ---------------------------------------------------------------------------
__global__ void __launch_bounds__(512, 1) gemm_mma(
    const __nv_bfloat16* __restrict__ Ah, const __nv_bfloat16* __restrict__ Al,
    const __nv_bfloat16* __restrict__ Bh, const __nv_bfloat16* __restrict__ Bl,
    float* __restrict__ C) {
    extern __shared__ char sm[];
    const uint32_t sb = smem_u32(sm);
    const int tid = threadIdx.x;
    const int wid = tid >> 5, lane = tid & 31;
    const int wm = (wid & 3) * 32;
    const int wn = (wid >> 2) * 64;
    const int ra = tid >> 2;          // loader row 0..127
    const int ca = tid & 3;           // loader 16B chunk 0..3
    const int m0 = blockIdx.y << 7;
    const int n0 = blockIdx.x << 8;

    GEMM_MAINLOOP(Ah, Al, Bh, Bl)

    const int er = lane >> 2;
    const int ec = (lane & 3) * 2;
#pragma unroll
    for (int a = 0; a < 2; a++) {
#pragma unroll
        for (int n = 0; n < 8; n++) {
            float* p0 = C + (size_t)(m0 + wm + a * 16 + er) * DMODEL + n0 + wn + n * 8 + ec;
            float* p1 = p0 + 8 * DMODEL;
            *reinterpret_cast<float2*>(p0) = make_float2(acc[a][n][0], acc[a][n][1]);
            *reinterpret_cast<float2*>(p1) = make_float2(acc[a][n][2], acc[a][n][3]);
        }
    }
}

// ---------------------------------------------------------------------------
// Fused QKV GEMM: grid (12, 32), N=3072 (Q|K|V; 256-wide CTAs never straddle).
// Epilogue applies RoPE to Q,K, folds 0.125*log2(e) into Q, writes split bf16.
// ---------------------------------------------------------------------------
__global__ void __launch_bounds__(512, 1) gemm_qkv(
    const __nv_bfloat16* __restrict__ Ah, const __nv_bfloat16* __restrict__ Al,
    const __nv_bfloat16* __restrict__ Bh, const __nv_bfloat16* __restrict__ Bl,
    const float2* __restrict__ tab,
    __nv_bfloat16* __restrict__ Qh, __nv_bfloat16* __restrict__ Ql,
    __nv_bfloat16* __restrict__ Kh, __nv_bfloat16* __restrict__ Kl,
    __nv_bfloat16* __restrict__ Vh, __nv_bfloat16* __restrict__ Vl) {
    extern __shared__ char sm[];
    const uint32_t sb = smem_u32(sm);
    const int tid = threadIdx.x;
    const int wid = tid >> 5, lane = tid & 31;
    const int wm = (wid & 3) * 32;
    const int wn = (wid >> 2) * 64;
    const int ra = tid >> 2;
    const int ca = tid & 3;
    const int m0 = blockIdx.y << 7;
    const int n0 = blockIdx.x << 8;

    GEMM_MAINLOOP(Ah, Al, Bh, Bl)

    const int er = lane >> 2;
    const int ec = (lane & 3) * 2;
    const int qkv = n0 >> 10;          // 0=Q, 1=K, 2=V (n0 multiple of 256)
    const int ncol = (n0 & 1023) + wn; // col offset within this output

    if (qkv < 2) {
        __nv_bfloat16* Dh = (qkv == 0) ? Qh : Kh;
        __nv_bfloat16* Dl = (qkv == 0) ? Ql : Kl;
        const float post = (qkv == 0) ? QSCALE_LOG2E : 1.0f;
#pragma unroll
        for (int a = 0; a < 2; a++) {
#pragma unroll
            for (int nf = 0; nf < 4; nf++) {   // pair (nf, nf+4) = cols jj, jj+32
                const int jj0 = nf * 8 + ec;
                const int dcol = ncol + nf * 8 + ec;
#pragma unroll
                for (int rs = 0; rs < 2; rs++) {
                    const int row = m0 + wm + a * 16 + er + rs * 8;
                    const float x1_0 = acc[a][nf][rs * 2 + 0];
                    const float x1_1 = acc[a][nf][rs * 2 + 1];
                    const float x2_0 = acc[a][nf + 4][rs * 2 + 0];
                    const float x2_1 = acc[a][nf + 4][rs * 2 + 1];
                    const float2 cs0 = tab[row * 32 + jj0];
                    const float2 cs1 = tab[row * 32 + jj0 + 1];
                    const float y1_0 = fmaf(x1_0, cs0.x, -x2_0 * cs0.y) * post;
                    const float y2_0 = fmaf(x2_0, cs0.x,  x1_0 * cs0.y) * post;
                    const float y1_1 = fmaf(x1_1, cs1.x, -x2_1 * cs1.y) * post;
                    const float y2_1 = fmaf(x2_1, cs1.x,  x1_1 * cs1.y) * post;
                    uint32_t h1, l1, h2, l2;
                    split2(y1_0, y1_1, h1, l1);
                    split2(y2_0, y2_1, h2, l2);
                    const size_t o1 = (size_t)row * DMODEL + dcol;
                    *reinterpret_cast<uint32_t*>(Dh + o1) = h1;
                    *reinterpret_cast<uint32_t*>(Dl + o1) = l1;
                    *reinterpret_cast<uint32_t*>(Dh + o1 + 32) = h2;
                    *reinterpret_cast<uint32_t*>(Dl + o1 + 32) = l2;
                }
            }
        }
    } else {
#pragma unroll
        for (int a = 0; a < 2; a++) {
#pragma unroll
            for (int nf = 0; nf < 8; nf++) {
                const int dcol = ncol + nf * 8 + ec;
#pragma unroll
                for (int rs = 0; rs < 2; rs++) {
                    const int row = m0 + wm + a * 16 + er + rs * 8;
                    uint32_t h, l;
                    split2(acc[a][nf][rs * 2 + 0], acc[a][nf][rs * 2 + 1], h, l);
                    const size_t o1 = (size_t)row * DMODEL + dcol;
                    *reinterpret_cast<uint32_t*>(Vh + o1) = h;
                    *reinterpret_cast<uint32_t*>(Vl + o1) = l;
                }
            }
        }
    }
}

// ---------------------------------------------------------------------------
// RoPE table precompute
// ---------------------------------------------------------------------------
__global__ void __launch_bounds__(256) rope_table_kernel(float2* __restrict__ tab) {
    int idx = blockIdx.x * 256 + threadIdx.x;  // 131072
    int row = idx >> 5, jj = idx & 31;
    float invf = (float)pow(10000.0, -(double)jj / 32.0);
    float ang = (float)row * invf;  // fp32 product like jax
    double s, c;
    sincos((double)ang, &s, &c);
    tab[idx] = make_float2((float)c, (float)s);
}

// ---------------------------------------------------------------------------
// HMMA flash attention, 256 threads (8 warps x 16 q-rows), 128-q tile.
// 2 CTAs/SM. Q pre-scaled by 0.125*log2(e) -> base-2 softmax via ex2.approx.
// ---------------------------------------------------------------------------
#define FLASH_SMEM 98304

__global__ void __launch_bounds__(256, 2) flash_mma(
    const __nv_bfloat16* __restrict__ Qh, const __nv_bfloat16* __restrict__ Ql,
    const __nv_bfloat16* __restrict__ Kh, const __nv_bfloat16* __restrict__ Kl,
    const __nv_bfloat16* __restrict__ Vh, const __nv_bfloat16* __restrict__ Vl,
    __nv_bfloat16* __restrict__ Oh, __nv_bfloat16* __restrict__ Ol) {
    extern __shared__ char sm[];
    const uint32_t sb = smem_u32(sm);
    const int tid = threadIdx.x;
    const int wid = tid >> 5, lane = tid & 31;

    // Work-ordered schedule: heavy CTAs dispatch first.
    const int bid = blockIdx.x;
    int h, qt;
    if (bid < 256) {           // full-attention heads: 64 kv tiles each
        h = 8 + (bid & 7);
        qt = bid >> 3;
    } else {                   // causal heads: descending qt (descending work)
        const int cid = bid - 256;
        qt = 31 - (cid >> 3);
        h = cid & 7;
    }
    const bool causal = (h < NAR);
    const int wm = wid * 16;

    // ---- load Q tile (128 rows, head slice), both splits ----
    {
        const int row = tid >> 1;
        const int chb = (tid & 1) * 4;
        const size_t g = (size_t)(qt * 128 + row) * DMODEL + h * DHEAD;
#pragma unroll
        for (int j = 0; j < 4; j++) {
            const uint32_t so = swz8(row, chb + j);
            CP16(sb + so, (const void*)(Qh + g + (chb + j) * 8));
            CP16(sb + 16384u + so, (const void*)(Ql + g + (chb + j) * 8));
        }
    }
    CP_COMMIT();

    const int ktiles = causal ? (2 * qt + 2) : (LSEQ / 64);

#define ISSUEKV(kt, buf)                                                        \
    do {                                                                        \
        const int _row = tid >> 2;                                              \
        const int _cb = (tid & 3) * 2;                                          \
        const uint32_t _sbb = sb + 32768u + (buf) * 32768u;                     \
        const size_t _g = (size_t)((kt) * 64 + _row) * DMODEL + h * DHEAD;      \
        _Pragma("unroll")                                                       \
        for (int _j = 0; _j < 2; _j++) {                                        \
            const uint32_t _so = swz8(_row, _cb + _j);                          \
            const size_t _e = _g + (_cb + _j) * 8;                              \
            CP16(_sbb + _so,           (const void*)(Kh + _e));                 \
            CP16(_sbb + 8192u + _so,   (const void*)(Kl + _e));                 \
            CP16(_sbb + 16384u + _so,  (const void*)(Vh + _e));                 \
            CP16(_sbb + 24576u + _so,  (const void*)(Vl + _e));                 \
        }                                                                       \
    } while (0)

    ISSUEKV(0, 0);
    CP_COMMIT();
    ISSUEKV(1, 1);
    CP_COMMIT();

    float o[8][4];
#pragma unroll
    for (int n = 0; n < 8; n++)
#pragma unroll
        for (int j = 0; j < 4; j++) o[n][j] = 0.0f;
    float m_[2] = {-1e30f, -1e30f};
    float l_[2] = {0.0f, 0.0f};

#pragma unroll 1
    for (int kt = 0; kt < ktiles; kt++) {
        if (kt < ktiles - 1)
            asm volatile("cp.async.wait_group 1;" ::: "memory");
        else
            asm volatile("cp.async.wait_group 0;" ::: "memory");
        __syncthreads();

        const uint32_t kbase = sb + 32768u + (kt & 1) * 32768u;
        const uint32_t vbase = kbase + 16384u;

        // ---- S = Q K^T (3 split terms); Q pre-scaled (base-2 domain) ----
        float sv[8][4];
#pragma unroll
        for (int n = 0; n < 8; n++)
#pragma unroll
            for (int j = 0; j < 4; j++) sv[n][j] = 0.0f;

#pragma unroll
        for (int ks = 0; ks < 4; ks++) {
            uint32_t ah[4], al[4];
            {
                const int row = wm + ((lane >> 3) & 1) * 8 + (lane & 7);
                const int ch = ks * 2 + (lane >> 4);
                const uint32_t off = swz8(row, ch);
                ldsm4(ah, sb + off);
                ldsm4(al, sb + 16384u + off);
            }
#pragma unroll
            for (int g = 0; g < 4; g++) {
                const int krow = g * 16 + ((lane >> 4) & 1) * 8 + (lane & 7);
                const int kch = ks * 2 + ((lane >> 3) & 1);
                const uint32_t off = swz8(krow, kch);
                uint32_t kh[4], kl[4];
                ldsm4(kh, kbase + off);
                MMA16816(sv[2 * g + 0], ah, kh + 0);
                MMA16816(sv[2 * g + 1], ah, kh + 2);
                MMA16816(sv[2 * g + 0], al, kh + 0);
                MMA16816(sv[2 * g + 1], al, kh + 2);
                ldsm4(kl, kbase + 8192u + off);
                MMA16816(sv[2 * g + 0], ah, kl + 0);
                MMA16816(sv[2 * g + 1], ah, kl + 2);
            }
        }

        // ---- causal mask ----
        if (causal && kt >= 2 * qt) {
#pragma unroll
            for (int half = 0; half < 2; half++) {
                const int qg = qt * 128 + wm + (lane >> 2) + half * 8;
#pragma unroll
                for (int nf = 0; nf < 8; nf++) {
#pragma unroll
                    for (int j = 0; j < 2; j++) {
                        const int kv = kt * 64 + nf * 8 + (lane & 3) * 2 + j;
                        if (kv > qg) sv[nf][half * 2 + j] = -1e30f;
                    }
                }
            }
        }

        // ---- online softmax, base-2 (2 rows per thread) ----
        float mnew[2];
#pragma unroll
        for (int half = 0; half < 2; half++) {
            float mx = -1e30f;
#pragma unroll
            for (int nf = 0; nf < 8; nf++)
                mx = fmaxf(mx, fmaxf(sv[nf][half * 2], sv[nf][half * 2 + 1]));
            mnew[half] = mx;
        }
#pragma unroll
        for (int r = 0; r < 2; r++) {
            mnew[r] = fmaxf(mnew[r], __shfl_xor_sync(0xffffffffu, mnew[r], 1));
            mnew[r] = fmaxf(mnew[r], __shfl_xor_sync(0xffffffffu, mnew[r], 2));
        }

        float alpha[2];
#pragma unroll
        for (int r = 0; r < 2; r++) {
            float mt = fmaxf(m_[r], mnew[r]);
            alpha[r] = ex2(m_[r] - mt);
            m_[r] = mt;
        }

        float rsum[2] = {0.0f, 0.0f};
#pragma unroll
        for (int nf = 0; nf < 8; nf++) {
#pragma unroll
            for (int half = 0; half < 2; half++) {
#pragma unroll
                for (int j = 0; j < 2; j++) {
                    float p = ex2(sv[nf][half * 2 + j] - m_[half]);
                    sv[nf][half * 2 + j] = p;
                    rsum[half] += p;
                }
            }
        }
#pragma unroll
        for (int r = 0; r < 2; r++) {
            rsum[r] += __shfl_xor_sync(0xffffffffu, rsum[r], 1);
            rsum[r] += __shfl_xor_sync(0xffffffffu, rsum[r], 2);
            l_[r] = l_[r] * alpha[r] + rsum[r];
        }

        // Rescale o only when the running max actually moved (warp vote).
        const bool need_rescale = (alpha[0] != 1.0f) || (alpha[1] != 1.0f);
        if (__any_sync(0xffffffffu, need_rescale)) {
#pragma unroll
            for (int nf = 0; nf < 8; nf++)
#pragma unroll
                for (int half = 0; half < 2; half++) {
                    o[nf][half * 2 + 0] *= alpha[half];
                    o[nf][half * 2 + 1] *= alpha[half];
                }
        }

        // ---- O += P V (3 split terms) ----
#pragma unroll
        for (int kg = 0; kg < 4; kg++) {
            uint32_t ph[4], pl[4];
#pragma unroll
            for (int q = 0; q < 2; q++) {
                const int nf = 2 * kg + q;
#pragma unroll
                for (int half = 0; half < 2; half++) {
                    float p0 = sv[nf][half * 2 + 0];
                    float p1 = sv[nf][half * 2 + 1];
                    split2(p0, p1, ph[q * 2 + half], pl[q * 2 + half]);
                }
            }
#pragma unroll
            for (int gd = 0; gd < 4; gd++) {
                const int vrow = kg * 16 + (lane & 15);
                const int vch = gd * 2 + (lane >> 4);
                const uint32_t off = swz8(vrow, vch);
                uint32_t vh[4], vl[4];
                ldsm4t(vh, vbase + off);
                MMA16816(o[2 * gd + 0], ph, vh + 0);
                MMA16816(o[2 * gd + 1], ph, vh + 2);
                MMA16816(o[2 * gd + 0], pl, vh + 0);
                MMA16816(o[2 * gd + 1], pl, vh + 2);
                ldsm4t(vl, vbase + 8192u + off);
                MMA16816(o[2 * gd + 0], ph, vl + 0);
                MMA16816(o[2 * gd + 1], ph, vl + 2);
            }
        }

        __syncthreads();
        if (kt + 2 < ktiles) {
            ISSUEKV(kt + 2, kt & 1);
            CP_COMMIT();
        }
    }
#undef ISSUEKV

    // ---- epilogue: normalize and store split bf16 O (into Ah/Al) ----
    const float inva = 1.0f / l_[0];
    const float invb = 1.0f / l_[1];
    const int rowa = qt * 128 + wm + (lane >> 2);
#pragma unroll
    for (int nf = 0; nf < 8; nf++) {
        const int col = h * DHEAD + nf * 8 + (lane & 3) * 2;
        uint32_t hA, lA, hB, lB;
        split2(o[nf][0] * inva, o[nf][1] * inva, hA, lA);
        split2(o[nf][2] * invb, o[nf][3] * invb, hB, lB);
        const size_t oa = (size_t)rowa * DMODEL + col;
        const size_t ob = oa + 8 * DMODEL;
        *reinterpret_cast<uint32_t*>(Oh + oa) = hA;
        *reinterpret_cast<uint32_t*>(Ol + oa) = lA;
        *reinterpret_cast<uint32_t*>(Oh + ob) = hB;
        *reinterpret_cast<uint32_t*>(Ol + ob) = lB;
    }
}

// ---------------------------------------------------------------------------
// Launch
// ---------------------------------------------------------------------------
extern "C" void kernel_launch(void* const* d_in, const int* in_sizes, int n_in,
                              void* d_out, int out_size) {
    const float* X  = (const float*)d_in[0];
    const float* Wq = (const float*)d_in[1];
    const float* Wk = (const float*)d_in[2];
    const float* Wv = (const float*)d_in[3];
    const float* Wo = (const float*)d_in[4];
    float* out = (float*)d_out;

    float2* ropep;
    __nv_bfloat16 *Ahp, *Alp, *Bthp, *Btlp;
    __nv_bfloat16 *Qhp, *Qlp, *Khp, *Klp, *Vhp, *Vlp;
    cudaGetSymbolAddress((void**)&ropep, g_rope);
    cudaGetSymbolAddress((void**)&Ahp, g_Ah);
    cudaGetSymbolAddress((void**)&Alp, g_Al);
    cudaGetSymbolAddress((void**)&Bthp, g_Bth);
    cudaGetSymbolAddress((void**)&Btlp, g_Btl);
    cudaGetSymbolAddress((void**)&Qhp, g_Qh);
    cudaGetSymbolAddress((void**)&Qlp, g_Ql);
    cudaGetSymbolAddress((void**)&Khp, g_Kh);
    cudaGetSymbolAddress((void**)&Klp, g_Kl);
    cudaGetSymbolAddress((void**)&Vhp, g_Vh);
    cudaGetSymbolAddress((void**)&Vlp, g_Vl);

    cudaFuncSetAttribute(gemm_mma, cudaFuncAttributeMaxDynamicSharedMemorySize,
                         GEMM_SMEM);
    cudaFuncSetAttribute(gemm_qkv, cudaFuncAttributeMaxDynamicSharedMemorySize,
                         GEMM_SMEM);
    cudaFuncSetAttribute(flash_mma, cudaFuncAttributeMaxDynamicSharedMemorySize,
                         FLASH_SMEM);

    const int splitA_blocks = (LSEQ * DMODEL / 4) / 256;  // 4096

    split_kernel<<<splitA_blocks, 256>>>(X, Ahp, Alp);
    rope_table_kernel<<<512, 256>>>(ropep);

    // All 4 weights transposed+split in one launch (Wo at slot 3)
    dim3 wt_grid(DMODEL / 32, DMODEL / 32, 4);  // (32, 32, 4)
    wsplit_all_kernel<<<wt_grid, 256>>>(Wq, Wk, Wv, Wo, Bthp, Btlp);

    // Fused QKV GEMM with rope+scale+split epilogue (128x256 tiles)
    dim3 qkv_grid(3 * DMODEL / 256, LSEQ / 128);  // (12, 32)
    gemm_qkv<<<qkv_grid, 512, GEMM_SMEM>>>(Ahp, Alp, Bthp, Btlp, ropep,
                                           Qhp, Qlp, Khp, Klp, Vhp, Vlp);

    // Flash attention; writes split O into Ah/Al. Work-ordered 1D grid.
    flash_mma<<<512, 256, FLASH_SMEM>>>(Qhp, Qlp, Khp, Klp, Vhp, Vlp,
                                        Ahp, Alp);

    // Final projection (Wo at slot 3), 128x256 tiles
    dim3 gemm_grid(DMODEL / 256, LSEQ / 128);  // (4, 32)
    gemm_mma<<<gemm_grid, 512, GEMM_SMEM>>>(Ahp, Alp,
                                            Bthp + 3 * DMODEL * DMODEL,
                                            Btlp + 3 * DMODEL * DMODEL, out);
}